// round 10
// baseline (speedup 1.0000x reference)
#include <cuda_runtime.h>

#define BB 256
#define TT 512
#define NT 128
#define GO_IDX 1
#define EOS_IDX 2
#define NEGV -10000.0f

// Scratch (allocation-free rule: __device__ globals)
__device__ float  g_alphas[BB * TT * NT];   // 64 MB alphas trajectory
__device__ float2 g_stats[BB * TT];         // per-(b,t) {rowmax, log(sum exp(u-rowmax))}
__device__ int    g_len[BB];                // normalized int32 lengths

// Packed fp32x2 helpers (B300 FADD2)
#define ADDX2(out, a, b) \
    asm("add.rn.f32x2 %0, %1, %2;" : "=l"(out) : "l"(a), "l"(b))
#define UNPK(lo, hi, v) \
    asm("mov.b64 {%0, %1}, %2;" : "=f"(lo), "=f"(hi) : "l"(v))
#define PK(out, lo, hi) \
    asm("mov.b64 %0, {%1, %2};" : "=l"(out) : "f"(lo), "f"(hi))

// ---------------------------------------------------------------------------
// Kernel 0: normalize lengths dtype (int32 vs int64) + defensive clamp.
// ---------------------------------------------------------------------------
__global__ void lens_kernel(const int* __restrict__ lens32) {
    int b = threadIdx.x;                     // 256 threads, 1 block
    bool is64 = (lens32[1] == 0);
    int v = is64 ? lens32[2 * b] : lens32[b];
    g_len[b] = min(max(v, 1), TT);
}

// ---------------------------------------------------------------------------
// Kernel A: per-row logsumexp stats (bandwidth bound, ~67MB read)
// ---------------------------------------------------------------------------
__global__ void stats_kernel(const float* __restrict__ u) {
    int warp = blockIdx.x * (blockDim.x >> 5) + (threadIdx.x >> 5);
    int lane = threadIdx.x & 31;
    if (warp >= BB * TT) return;
    const float4* row = reinterpret_cast<const float4*>(u + (size_t)warp * NT);
    float4 v = row[lane];
    float m = fmaxf(fmaxf(v.x, v.y), fmaxf(v.z, v.w));
    #pragma unroll
    for (int o = 16; o; o >>= 1) m = fmaxf(m, __shfl_xor_sync(0xffffffffu, m, o));
    float s = expf(v.x - m) + expf(v.y - m) + expf(v.z - m) + expf(v.w - m);
    #pragma unroll
    for (int o = 16; o; o >>= 1) s += __shfl_xor_sync(0xffffffffu, s, o);
    if (lane == 0) g_stats[warp] = make_float2(m, logf(s));
}

// ---------------------------------------------------------------------------
// Kernel B: forward Viterbi. 256-thread block = TWO INDEPENDENT batches:
// threads 0-127 run batch 2*bid with named barrier 1, threads 128-255 run
// batch 2*bid+1 with named barrier 2. Grid=128 -> exactly one block per SM,
// uniform load; each SMSP hosts two warps from independent recurrences, so
// barrier waits and LDS latency of one batch are hidden by the other's
// issues. Per-thread work identical to the R4-proven form.
// ---------------------------------------------------------------------------
__global__ __launch_bounds__(256) void forward_kernel(
    const float* __restrict__ u,
    const float* __restrict__ trans)
{
    int grp = threadIdx.x >> 7;          // 0 or 1: which batch
    int cur = threadIdx.x & 127;         // tag
    int b   = 2 * blockIdx.x + grp;
    int bar = grp + 1;                   // named barrier id (1 or 2)

    // pack this tag's transition row into 64 fp32x2 register pairs
    unsigned long long rt2[NT / 2];
    const float2* tr2 = reinterpret_cast<const float2*>(trans + cur * NT);
    #pragma unroll
    for (int j = 0; j < NT / 2; j++) {
        float2 v = __ldg(tr2 + j);
        PK(rt2[j], v.x, v.y);
    }

    __shared__ __align__(16) float abuf[2][2][NT];   // [grp][parity][tag]
    abuf[grp][0][cur] = (cur == GO_IDX) ? 0.0f : NEGV;  // exact log_softmax init

    int len = g_len[b];
    const float*  ub = u + (size_t)b * TT * NT;
    const float2* st = g_stats + (size_t)b * TT;
    float*        ao = g_alphas + (size_t)b * TT * NT;

    asm volatile("bar.sync %0, 128;" :: "r"(bar) : "memory");

    float  uv = ub[cur];
    float2 s  = st[0];

    for (int t = 0; t < len; t++) {
        // prefetch next step (clamped index -> always in-bounds)
        int tn = (t + 1 < len) ? (t + 1) : t;
        float  nuv = ub[tn * NT + cur];
        float2 ns  = st[tn];

        const ulonglong2* a2 = reinterpret_cast<const ulonglong2*>(abuf[grp][t & 1]);
        float m0 = -3.4e38f, m1 = -3.4e38f, m2 = -3.4e38f, m3 = -3.4e38f;
        #pragma unroll
        for (int q = 0; q < NT / 4; q++) {
            ulonglong2 p = a2[q];            // LDS.128 broadcast
            unsigned long long s0, s1;
            ADDX2(s0, p.x, rt2[2 * q]);      // 2 adds per issue
            ADDX2(s1, p.y, rt2[2 * q + 1]);
            float f0, f1, f2, f3;
            UNPK(f0, f1, s0);
            UNPK(f2, f3, s1);
            m0 = fmaxf(m0, f0);
            m1 = fmaxf(m1, f1);
            m2 = fmaxf(m2, f2);
            m3 = fmaxf(m3, f3);
        }
        float m = fmaxf(fmaxf(m0, m1), fmaxf(m2, m3));
        // probv = (u - rowmax) - L  (matches reference log_softmax arithmetic;
        // ULP error in L is uniform across tags -> decisions invariant)
        float na = m + ((uv - s.x) - s.y);
        abuf[grp][(t + 1) & 1][cur] = na;
        ao[t * NT + cur] = na;
        asm volatile("bar.sync %0, 128;" :: "r"(bar) : "memory");
        uv = nuv; s = ns;
    }
}

// ---------------------------------------------------------------------------
// Kernel C: terminal argmax + backtrace. trans table in 64KB dynamic smem
// (unevictable, LDS=29cyc on the tag-dependent serial-chain load). Warp 0
// runs the chain with chunked MLP=8 double-buffered __ldcs alphas prefetch.
// ---------------------------------------------------------------------------
__device__ __forceinline__ unsigned fmono(float f) {
    unsigned u = __float_as_uint(f);
    int s = ((int)u) >> 31;
    return u ^ (unsigned)(s | 0x80000000);
}
__device__ __forceinline__ float fmono_inv(unsigned m) {
    return (m & 0x80000000u) ? __uint_as_float(m & 0x7fffffffu)
                             : __uint_as_float(~m);
}

__global__ __launch_bounds__(128) void backtrace_kernel(
    const float* __restrict__ trans,
    float* __restrict__ out)
{
    extern __shared__ __align__(16) float strans[];   // 64KB: full trans table
    int b = blockIdx.x;
    int tid = threadIdx.x;
    int len = g_len[b];
    float* preds = out + (size_t)b * TT;

    // cooperative copy trans -> smem (4096 float4, 32 per thread)
    const float4* t4 = reinterpret_cast<const float4*>(trans);
    float4* s4 = reinterpret_cast<float4*>(strans);
    #pragma unroll
    for (int i = 0; i < (NT * NT / 4) / 128; i++)
        s4[tid + i * 128] = __ldg(t4 + tid + i * 128);

    // preds[t] = 0 for t >= len
    for (int t = len + tid; t < TT; t += 128) preds[t] = 0.0f;
    __syncthreads();

    if (tid >= 32) return;   // warps 1-3 done
    int lane = tid;

    const float* ab = g_alphas + (size_t)b * TT * NT;

    // terminal: argmax_cur( alphas[len-1][cur] + trans[EOS][cur] ), first-max ties
    float4 a  = __ldcs(reinterpret_cast<const float4*>(ab + (size_t)(len - 1) * NT) + lane);
    float4 tv = reinterpret_cast<const float4*>(strans + EOS_IDX * NT)[lane];
    unsigned c0 = fmono(a.x + tv.x), c1 = fmono(a.y + tv.y);
    unsigned c2 = fmono(a.z + tv.z), c3 = fmono(a.w + tv.w);
    unsigned best = max(max(c0, c1), max(c2, c3));
    unsigned wmax = __reduce_max_sync(0xffffffffu, best);
    unsigned idx = 0x7fffffffu;
    if (c3 == wmax) idx = 4u * lane + 3u;
    if (c2 == wmax) idx = 4u * lane + 2u;
    if (c1 == wmax) idx = 4u * lane + 1u;
    if (c0 == wmax) idx = 4u * lane + 0u;
    int tag = (int)__reduce_min_sync(0xffffffffu, idx);
    if (lane == 0) {
        out[(size_t)BB * TT + b] = fmono_inv(wmax);  // path score (exact max)
        preds[len - 1] = (float)tag;
    }

    // chase rows R_i = len-2-i for i in [0, nrows); chunked prefetch depth 8
    int nrows = len - 1;
    int nchunks = (nrows + 7) >> 3;
    float4 bufA[8], bufB[8];

#define BT_LOAD(DST, C)                                                        \
    {                                                                          \
        _Pragma("unroll")                                                      \
        for (int k = 0; k < 8; k++) {                                          \
            int i = 8 * (C) + k;                                               \
            if (i < nrows)                                                     \
                DST[k] = __ldcs(reinterpret_cast<const float4*>(               \
                             ab + (size_t)(len - 2 - i) * NT) + lane);         \
        }                                                                      \
    }

#define BT_PROC(SRC, C)                                                        \
    {                                                                          \
        _Pragma("unroll")                                                      \
        for (int k = 0; k < 8; k++) {                                          \
            int i = 8 * (C) + k;                                               \
            if (i >= nrows) break;                                             \
            float4 av = SRC[k];                                                \
            float4 tr = reinterpret_cast<const float4*>(                       \
                            strans + tag * NT)[lane];                          \
            c0 = fmono(av.x + tr.x); c1 = fmono(av.y + tr.y);                  \
            c2 = fmono(av.z + tr.z); c3 = fmono(av.w + tr.w);                  \
            best = max(max(c0, c1), max(c2, c3));                              \
            wmax = __reduce_max_sync(0xffffffffu, best);                       \
            idx = 0x7fffffffu;                                                 \
            if (c3 == wmax) idx = 4u * lane + 3u;                              \
            if (c2 == wmax) idx = 4u * lane + 2u;                              \
            if (c1 == wmax) idx = 4u * lane + 1u;                              \
            if (c0 == wmax) idx = 4u * lane + 0u;                              \
            tag = (int)__reduce_min_sync(0xffffffffu, idx);                    \
            if (lane == 0) preds[len - 2 - i] = (float)tag;                    \
        }                                                                      \
    }

    if (nchunks > 0) BT_LOAD(bufA, 0);
    for (int c = 0; c < nchunks; c++) {
        if ((c & 1) == 0) {
            if (c + 1 < nchunks) BT_LOAD(bufB, c + 1);
            BT_PROC(bufA, c);
        } else {
            if (c + 1 < nchunks) BT_LOAD(bufA, c + 1);
            BT_PROC(bufB, c);
        }
    }
#undef BT_LOAD
#undef BT_PROC
}

// ---------------------------------------------------------------------------
extern "C" void kernel_launch(void* const* d_in, const int* in_sizes, int n_in,
                              void* d_out, int out_size)
{
    const float* u     = (const float*)d_in[0];   // unaries [B,T,N] f32
    const float* trans = (const float*)d_in[1];   // trans  [1,N,N] f32
    const int*   lens  = (const int*)d_in[2];     // lengths [B] (i32 or i64, detected)
    float* out = (float*)d_out;                   // [B*T preds | B scores]

    // 64KB dynamic smem for the trans table (idempotent attribute set)
    cudaFuncSetAttribute(backtrace_kernel,
                         cudaFuncAttributeMaxDynamicSharedMemorySize,
                         NT * NT * (int)sizeof(float));

    lens_kernel<<<1, BB>>>(lens);
    stats_kernel<<<(BB * TT) / 8, 256>>>(u);
    forward_kernel<<<BB / 2, 256>>>(u, trans);
    backtrace_kernel<<<BB, 128, NT * NT * sizeof(float)>>>(trans, out);
}

// round 14
// speedup vs baseline: 1.3155x; 1.3155x over previous
#include <cuda_runtime.h>

#define BB 256
#define TT 512
#define NT 128
#define GO_IDX 1
#define EOS_IDX 2
#define NEGV -10000.0f

// Scratch (allocation-free rule: __device__ globals)
__device__ float  g_alphas[BB * TT * NT];   // 64 MB alphas trajectory
__device__ float2 g_stats[BB * TT];         // per-(b,t) {rowmax, log(sum exp(u-rowmax))}
__device__ int    g_len[BB];                // normalized int32 lengths
__device__ int    g_perm[BB];               // batch ids sorted by length DESC

// Packed fp32x2 helpers (Blackwell f32x2: add/sub/mul/fma only — NO max)
#define ADDX2(out, a, b) \
    asm("add.rn.f32x2 %0, %1, %2;" : "=l"(out) : "l"(a), "l"(b))
#define UNPK(lo, hi, v) \
    asm("mov.b64 {%0, %1}, %2;" : "=f"(lo), "=f"(hi) : "l"(v))
#define PK(out, lo, hi) \
    asm("mov.b64 %0, {%1, %2};" : "=l"(out) : "f"(lo), "f"(hi))

// ---------------------------------------------------------------------------
// Kernel 0: normalize lengths dtype (int32 vs int64, detected) + clamp, then
// rank batches by length DESC (stable). Forward blocks take batches in this
// order so wave 1 (148 blocks) gets the longest sequences and wave 2 the
// shortest -> per-SM serial time drops from ~2*E[len] to ~max_len+min_len.
// ---------------------------------------------------------------------------
__global__ void lens_kernel(const int* __restrict__ lens32) {
    __shared__ int sl[BB];
    int b = threadIdx.x;                     // 256 threads, 1 block
    bool is64 = (lens32[1] == 0);
    int v = is64 ? lens32[2 * b] : lens32[b];
    v = min(max(v, 1), TT);
    g_len[b] = v;
    sl[b] = v;
    __syncthreads();
    // rank = #batches strictly longer + ties with smaller id (unique)
    int rank = 0;
    #pragma unroll 8
    for (int j = 0; j < BB; j++) {
        int lj = sl[j];
        rank += (lj > v) || (lj == v && j < b);
    }
    g_perm[rank] = b;
}

// ---------------------------------------------------------------------------
// Kernel A: per-row logsumexp stats (bandwidth bound, ~67MB read)
// ---------------------------------------------------------------------------
__global__ void stats_kernel(const float* __restrict__ u) {
    int warp = blockIdx.x * (blockDim.x >> 5) + (threadIdx.x >> 5);
    int lane = threadIdx.x & 31;
    if (warp >= BB * TT) return;
    const float4* row = reinterpret_cast<const float4*>(u + (size_t)warp * NT);
    float4 v = row[lane];
    float m = fmaxf(fmaxf(v.x, v.y), fmaxf(v.z, v.w));
    #pragma unroll
    for (int o = 16; o; o >>= 1) m = fmaxf(m, __shfl_xor_sync(0xffffffffu, m, o));
    float s = expf(v.x - m) + expf(v.y - m) + expf(v.z - m) + expf(v.w - m);
    #pragma unroll
    for (int o = 16; o; o >>= 1) s += __shfl_xor_sync(0xffffffffu, s, o);
    if (lane == 0) g_stats[warp] = make_float2(m, logf(s));
}

// ---------------------------------------------------------------------------
// Kernel B: forward Viterbi (proven shape: 1 block = 1 batch, 128 threads,
// __syncthreads). Batch picked via g_perm for wave balancing. Inner loop:
// 32 x (LDS.128 + 2 ADD.f32x2 + 4 FMNMX) — packed adds halve the fma-pipe
// issues; maxes stay scalar (no packed max on sm_103a). uv/stats prefetched
// TWO steps ahead (clamped) so the LDG never lands on the step chain.
// ---------------------------------------------------------------------------
__global__ __launch_bounds__(128) void forward_kernel(
    const float* __restrict__ u,
    const float* __restrict__ trans)
{
    int b = g_perm[blockIdx.x];
    int cur = threadIdx.x;

    // pack this tag's transition row into 64 fp32x2 register pairs
    unsigned long long rt2[NT / 2];
    const float2* tr2 = reinterpret_cast<const float2*>(trans + cur * NT);
    #pragma unroll
    for (int j = 0; j < NT / 2; j++) {
        float2 v = __ldg(tr2 + j);
        PK(rt2[j], v.x, v.y);
    }

    __shared__ __align__(16) float abuf[2][NT];
    abuf[0][cur] = (cur == GO_IDX) ? 0.0f : NEGV;   // exact log_softmax of init

    int len = g_len[b];
    const float*  ub = u + (size_t)b * TT * NT;
    const float2* st = g_stats + (size_t)b * TT;
    float*        ao = g_alphas + (size_t)b * TT * NT;
    __syncthreads();

    // depth-2 software pipeline on uv / stats (clamped indices, in-bounds)
    float  uv0 = ub[cur];
    float2 s0  = st[0];
    int    t1  = (1 < len) ? 1 : 0;
    float  uv1 = ub[t1 * NT + cur];
    float2 s1  = st[t1];

    for (int t = 0; t < len; t++) {
        // prefetch step t+2 (clamped)
        int tn = (t + 2 < len) ? (t + 2) : (len - 1);
        float  nuv = __ldcs(ub + tn * NT + cur);
        float2 ns  = st[tn];

        const ulonglong2* a2 = reinterpret_cast<const ulonglong2*>(abuf[t & 1]);
        float m0 = -3.4e38f, m1 = -3.4e38f, m2 = -3.4e38f, m3 = -3.4e38f;
        #pragma unroll
        for (int q = 0; q < NT / 4; q++) {
            ulonglong2 p = a2[q];            // LDS.128 broadcast
            unsigned long long v0, v1;
            ADDX2(v0, p.x, rt2[2 * q]);      // 2 adds per issue
            ADDX2(v1, p.y, rt2[2 * q + 1]);
            float f0, f1, f2, f3;
            UNPK(f0, f1, v0);                // free register renames
            UNPK(f2, f3, v1);
            m0 = fmaxf(m0, f0);
            m1 = fmaxf(m1, f1);
            m2 = fmaxf(m2, f2);
            m3 = fmaxf(m3, f3);
        }
        float m = fmaxf(fmaxf(m0, m1), fmaxf(m2, m3));
        // probv = (u - rowmax) - L  (matches reference log_softmax arithmetic;
        // ULP error in L is uniform across tags -> decisions invariant)
        float na = m + ((uv0 - s0.x) - s0.y);
        abuf[(t + 1) & 1][cur] = na;
        ao[t * NT + cur] = na;
        __syncthreads();
        uv0 = uv1; s0 = s1;
        uv1 = nuv; s1 = ns;
    }
}

// ---------------------------------------------------------------------------
// Kernel C: terminal argmax + backtrace. trans table in 64KB dynamic smem
// (unevictable, LDS=29cyc on the tag-dependent serial-chain load). Warp 0
// runs the chain with chunked MLP=8 double-buffered __ldcs alphas prefetch.
// ---------------------------------------------------------------------------
__device__ __forceinline__ unsigned fmono(float f) {
    unsigned u = __float_as_uint(f);
    int s = ((int)u) >> 31;
    return u ^ (unsigned)(s | 0x80000000);
}
__device__ __forceinline__ float fmono_inv(unsigned m) {
    return (m & 0x80000000u) ? __uint_as_float(m & 0x7fffffffu)
                             : __uint_as_float(~m);
}

__global__ __launch_bounds__(128) void backtrace_kernel(
    const float* __restrict__ trans,
    float* __restrict__ out)
{
    extern __shared__ __align__(16) float strans[];   // 64KB: full trans table
    int b = blockIdx.x;
    int tid = threadIdx.x;
    int len = g_len[b];
    float* preds = out + (size_t)b * TT;

    // cooperative copy trans -> smem (4096 float4, 32 per thread)
    const float4* t4 = reinterpret_cast<const float4*>(trans);
    float4* s4 = reinterpret_cast<float4*>(strans);
    #pragma unroll
    for (int i = 0; i < (NT * NT / 4) / 128; i++)
        s4[tid + i * 128] = __ldg(t4 + tid + i * 128);

    // preds[t] = 0 for t >= len
    for (int t = len + tid; t < TT; t += 128) preds[t] = 0.0f;
    __syncthreads();

    if (tid >= 32) return;   // warps 1-3 done
    int lane = tid;

    const float* ab = g_alphas + (size_t)b * TT * NT;

    // terminal: argmax_cur( alphas[len-1][cur] + trans[EOS][cur] ), first-max ties
    float4 a  = __ldcs(reinterpret_cast<const float4*>(ab + (size_t)(len - 1) * NT) + lane);
    float4 tv = reinterpret_cast<const float4*>(strans + EOS_IDX * NT)[lane];
    unsigned c0 = fmono(a.x + tv.x), c1 = fmono(a.y + tv.y);
    unsigned c2 = fmono(a.z + tv.z), c3 = fmono(a.w + tv.w);
    unsigned best = max(max(c0, c1), max(c2, c3));
    unsigned wmax = __reduce_max_sync(0xffffffffu, best);
    unsigned idx = 0x7fffffffu;
    if (c3 == wmax) idx = 4u * lane + 3u;
    if (c2 == wmax) idx = 4u * lane + 2u;
    if (c1 == wmax) idx = 4u * lane + 1u;
    if (c0 == wmax) idx = 4u * lane + 0u;
    int tag = (int)__reduce_min_sync(0xffffffffu, idx);
    if (lane == 0) {
        out[(size_t)BB * TT + b] = fmono_inv(wmax);  // path score (exact max)
        preds[len - 1] = (float)tag;
    }

    // chase rows R_i = len-2-i for i in [0, nrows); chunked prefetch depth 8
    int nrows = len - 1;
    int nchunks = (nrows + 7) >> 3;
    float4 bufA[8], bufB[8];

#define BT_LOAD(DST, C)                                                        \
    {                                                                          \
        _Pragma("unroll")                                                      \
        for (int k = 0; k < 8; k++) {                                          \
            int i = 8 * (C) + k;                                               \
            if (i < nrows)                                                     \
                DST[k] = __ldcs(reinterpret_cast<const float4*>(               \
                             ab + (size_t)(len - 2 - i) * NT) + lane);         \
        }                                                                      \
    }

#define BT_PROC(SRC, C)                                                        \
    {                                                                          \
        _Pragma("unroll")                                                      \
        for (int k = 0; k < 8; k++) {                                          \
            int i = 8 * (C) + k;                                               \
            if (i >= nrows) break;                                             \
            float4 av = SRC[k];                                                \
            float4 tr = reinterpret_cast<const float4*>(                       \
                            strans + tag * NT)[lane];                          \
            c0 = fmono(av.x + tr.x); c1 = fmono(av.y + tr.y);                  \
            c2 = fmono(av.z + tr.z); c3 = fmono(av.w + tr.w);                  \
            best = max(max(c0, c1), max(c2, c3));                              \
            wmax = __reduce_max_sync(0xffffffffu, best);                       \
            idx = 0x7fffffffu;                                                 \
            if (c3 == wmax) idx = 4u * lane + 3u;                              \
            if (c2 == wmax) idx = 4u * lane + 2u;                              \
            if (c1 == wmax) idx = 4u * lane + 1u;                              \
            if (c0 == wmax) idx = 4u * lane + 0u;                              \
            tag = (int)__reduce_min_sync(0xffffffffu, idx);                    \
            if (lane == 0) preds[len - 2 - i] = (float)tag;                    \
        }                                                                      \
    }

    if (nchunks > 0) BT_LOAD(bufA, 0);
    for (int c = 0; c < nchunks; c++) {
        if ((c & 1) == 0) {
            if (c + 1 < nchunks) BT_LOAD(bufB, c + 1);
            BT_PROC(bufA, c);
        } else {
            if (c + 1 < nchunks) BT_LOAD(bufA, c + 1);
            BT_PROC(bufB, c);
        }
    }
#undef BT_LOAD
#undef BT_PROC
}

// ---------------------------------------------------------------------------
extern "C" void kernel_launch(void* const* d_in, const int* in_sizes, int n_in,
                              void* d_out, int out_size)
{
    const float* u     = (const float*)d_in[0];   // unaries [B,T,N] f32
    const float* trans = (const float*)d_in[1];   // trans  [1,N,N] f32
    const int*   lens  = (const int*)d_in[2];     // lengths [B] (i32 or i64, detected)
    float* out = (float*)d_out;                   // [B*T preds | B scores]

    // 64KB dynamic smem for the trans table (idempotent attribute set)
    cudaFuncSetAttribute(backtrace_kernel,
                         cudaFuncAttributeMaxDynamicSharedMemorySize,
                         NT * NT * (int)sizeof(float));

    lens_kernel<<<1, BB>>>(lens);
    stats_kernel<<<(BB * TT) / 8, 256>>>(u);
    forward_kernel<<<BB, 128>>>(u, trans);
    backtrace_kernel<<<BB, 128, NT * NT * sizeof(float)>>>(trans, out);
}

// round 16
// speedup vs baseline: 1.7674x; 1.3435x over previous
#include <cuda_runtime.h>

#define BB 256
#define TT 512
#define NT 128
#define GO_IDX 1
#define EOS_IDX 2
#define NEGV -10000.0f

// Scratch (allocation-free rule: __device__ globals)
__device__ float  g_alphas[BB * TT * NT];   // 64 MB alphas trajectory
__device__ float2 g_stats[BB * TT];         // per-(b,t) {rowmax, logsumexp}
__device__ int    g_len[BB];                // normalized int32 lengths
__device__ int    g_perm[BB];               // batch ids sorted by length DESC
__device__ float  g_tv[NT], g_ti[NT];       // per-column max/min of trans (2-value structure)
__device__ unsigned char g_nib[NT * 32];    // per (cur, quad) 4-bit selection index

// Packed fp32x2 helpers (Blackwell f32x2: add/sub/mul/fma only — NO max)
#define ADDX2(out, a, b) \
    asm("add.rn.f32x2 %0, %1, %2;" : "=l"(out) : "l"(a), "l"(b))
#define UNPK(lo, hi, v) \
    asm("mov.b64 {%0, %1}, %2;" : "=f"(lo), "=f"(hi) : "l"(v))
#define PK(out, lo, hi) \
    asm("mov.b64 %0, {%1, %2};" : "=l"(out) : "f"(lo), "f"(hi))

// ---------------------------------------------------------------------------
// Kernel 0: normalize lengths dtype (int32 vs int64, detected) + clamp, then
// rank batches by length DESC (stable) for forward wave balancing.
// ---------------------------------------------------------------------------
__global__ void lens_kernel(const int* __restrict__ lens32) {
    __shared__ int sl[BB];
    int b = threadIdx.x;                     // 256 threads, 1 block
    bool is64 = (lens32[1] == 0);
    int v = is64 ? lens32[2 * b] : lens32[b];
    v = min(max(v, 1), TT);
    g_len[b] = v;
    sl[b] = v;
    __syncthreads();
    int rank = 0;
    #pragma unroll 8
    for (int j = 0; j < BB; j++) {
        int lj = sl[j];
        rank += (lj > v) || (lj == v && j < b);
    }
    g_perm[rank] = b;
}

// ---------------------------------------------------------------------------
// Kernel P: extract the 2-value column structure of trans.
// Each column p of trans[c][p] holds exactly two floats: tv_p (valid rows)
// and ti_p (invalid rows), because trans = log_softmax(mask ? -1e4 : 0).
// nib(c,q) bit j = 1 iff trans[c][4q+j] == ti_{4q+j} (select the B value).
// If a column is uniform, tv==ti and either selection is exact. One block.
// ---------------------------------------------------------------------------
__global__ void prep_kernel(const float* __restrict__ trans) {
    extern __shared__ __align__(16) float tr[];   // 64KB trans copy
    __shared__ float sti[NT];
    int tid = threadIdx.x;                        // 128 threads
    const float4* t4 = reinterpret_cast<const float4*>(trans);
    float4* s4 = reinterpret_cast<float4*>(tr);
    #pragma unroll
    for (int i = 0; i < (NT * NT / 4) / 128; i++)
        s4[tid + i * 128] = __ldg(t4 + tid + i * 128);
    __syncthreads();
    // column tid: min / max (conflict-free: lane-distinct banks)
    float ti = 3.4e38f, tv = -3.4e38f;
    for (int c = 0; c < NT; c++) {
        float v = tr[c * NT + tid];
        ti = fminf(ti, v);
        tv = fmaxf(tv, v);
    }
    g_tv[tid] = tv;
    g_ti[tid] = ti;
    sti[tid] = ti;
    __syncthreads();
    // row tid (= cur): 32 nibbles
    for (int q = 0; q < 32; q++) {
        int nib = 0;
        #pragma unroll
        for (int j = 0; j < 4; j++) {
            int p = 4 * q + j;
            if (tr[tid * NT + p] == sti[p]) nib |= 1 << j;
        }
        g_nib[tid * 32 + q] = (unsigned char)nib;
    }
}

// ---------------------------------------------------------------------------
// Kernel A: per-row logsumexp stats (bandwidth bound, ~67MB read)
// ---------------------------------------------------------------------------
__global__ void stats_kernel(const float* __restrict__ u) {
    int warp = blockIdx.x * (blockDim.x >> 5) + (threadIdx.x >> 5);
    int lane = threadIdx.x & 31;
    if (warp >= BB * TT) return;
    const float4* row = reinterpret_cast<const float4*>(u + (size_t)warp * NT);
    float4 v = row[lane];
    float m = fmaxf(fmaxf(v.x, v.y), fmaxf(v.z, v.w));
    #pragma unroll
    for (int o = 16; o; o >>= 1) m = fmaxf(m, __shfl_xor_sync(0xffffffffu, m, o));
    float s = expf(v.x - m) + expf(v.y - m) + expf(v.z - m) + expf(v.w - m);
    #pragma unroll
    for (int o = 16; o; o >>= 1) s += __shfl_xor_sync(0xffffffffu, s, o);
    if (lane == 0) g_stats[warp] = make_float2(m, logf(s));
}

// ---------------------------------------------------------------------------
// Kernel B: forward Viterbi with shared quad-max tables.
// Per step: each thread builds 4 entries of its quad's table
// T[q][e] = max_j ((e>>j&1) ? a+ti : a+tv)_{4q+j}  (exact reference addends,
// shared across all 128 curs), then computes its cur's new alpha as
// max over q of T[q][nib(cur,q)] : 32 conflict-free LDS + 31 FMNMX instead
// of 128 FADD + 128 FMNMX. fp-max is order-exact -> alphas bitwise identical.
// ---------------------------------------------------------------------------
__global__ __launch_bounds__(128) void forward_kernel(const float* __restrict__ u)
{
    int b   = g_perm[blockIdx.x];
    int cur = threadIdx.x;
    int qo  = cur >> 2;      // quad this thread helps build
    int sub = cur & 3;       // entry group (entries sub*4 .. sub*4+3)

    __shared__ __align__(16) float salpha[NT];
    __shared__ __align__(16) float stbl[32 * 16];   // 2KB quad tables

    // static per-thread preloads
    float4 tvq = *reinterpret_cast<const float4*>(g_tv + 4 * qo);
    float4 tiq = *reinterpret_cast<const float4*>(g_ti + 4 * qo);
    unsigned long long tv01, tv23, ti01, ti23;
    PK(tv01, tvq.x, tvq.y); PK(tv23, tvq.z, tvq.w);
    PK(ti01, tiq.x, tiq.y); PK(ti23, tiq.z, tiq.w);
    bool p2 = (sub & 1) != 0, p3 = (sub >> 1) != 0;  // entry bits j=2,3

    // lookup addresses (static: nibbles are a function of trans only)
    unsigned stbl_u = (unsigned)__cvta_generic_to_shared(stbl);
    const uint4* nb = reinterpret_cast<const uint4*>(g_nib + cur * 32);
    uint4 n0 = __ldg(nb), n1 = __ldg(nb + 1);
    unsigned nw[8] = {n0.x, n0.y, n0.z, n0.w, n1.x, n1.y, n1.z, n1.w};
    unsigned addr[32];
    #pragma unroll
    for (int q = 0; q < 32; q++) {
        unsigned nib = (nw[q >> 2] >> ((q & 3) * 8)) & 0xffu;
        addr[q] = stbl_u + (q * 16 + nib) * 4;
    }

    salpha[cur] = (cur == GO_IDX) ? 0.0f : NEGV;    // exact log_softmax init
    int len = g_len[b];
    const float*  ub = u + (size_t)b * TT * NT;
    const float2* st = g_stats + (size_t)b * TT;
    float*        ao = g_alphas + (size_t)b * TT * NT;
    __syncthreads();

    // depth-2 software pipeline on uv / stats (clamped indices, in-bounds)
    float  uv0 = ub[cur];
    float2 s0  = st[0];
    int    t1  = (1 < len) ? 1 : 0;
    float  uv1 = ub[t1 * NT + cur];
    float2 s1  = st[t1];

    for (int t = 0; t < len; t++) {
        // prefetch step t+2 (clamped)
        int tn = (t + 2 < len) ? (t + 2) : (len - 1);
        float  nuv = __ldcs(ub + tn * NT + cur);
        float2 ns  = st[tn];

        // ---- build own quad-table entries (alphas valid here) ----
        float4 a4 = *reinterpret_cast<const float4*>(salpha + 4 * qo);
        unsigned long long a01, a23, A01, A23, B01, B23;
        PK(a01, a4.x, a4.y); PK(a23, a4.z, a4.w);
        ADDX2(A01, a01, tv01); ADDX2(A23, a23, tv23);   // A_p = a_p + tv_p
        ADDX2(B01, a01, ti01); ADDX2(B23, a23, ti23);   // B_p = a_p + ti_p
        float A0, A1, A2, A3, B0, B1, B2, B3;
        UNPK(A0, A1, A01); UNPK(A2, A3, A23);
        UNPK(B0, B1, B01); UNPK(B2, B3, B23);
        float V2 = p2 ? B2 : A2;
        float V3 = p3 ? B3 : A3;
        float W  = fmaxf(V2, V3);                       // shared by 4 entries
        float4 ent;
        ent.x = fmaxf(fmaxf(A0, A1), W);                // e = sub*4+0
        ent.y = fmaxf(fmaxf(B0, A1), W);                // e = sub*4+1
        ent.z = fmaxf(fmaxf(A0, B1), W);                // e = sub*4+2
        ent.w = fmaxf(fmaxf(B0, B1), W);                // e = sub*4+3
        *reinterpret_cast<float4*>(stbl + qo * 16 + sub * 4) = ent;
        __syncthreads();                                // tables ready

        // ---- per-cur lookup reduction ----
        float m0 = -3.4e38f, m1 = -3.4e38f, m2 = -3.4e38f, m3 = -3.4e38f;
        #pragma unroll
        for (int q = 0; q < 32; q += 4) {
            float v0, v1, v2, v3;
            asm volatile("ld.shared.f32 %0, [%1];" : "=f"(v0) : "r"(addr[q + 0]));
            asm volatile("ld.shared.f32 %0, [%1];" : "=f"(v1) : "r"(addr[q + 1]));
            asm volatile("ld.shared.f32 %0, [%1];" : "=f"(v2) : "r"(addr[q + 2]));
            asm volatile("ld.shared.f32 %0, [%1];" : "=f"(v3) : "r"(addr[q + 3]));
            m0 = fmaxf(m0, v0);
            m1 = fmaxf(m1, v1);
            m2 = fmaxf(m2, v2);
            m3 = fmaxf(m3, v3);
        }
        float m = fmaxf(fmaxf(m0, m1), fmaxf(m2, m3));
        // probv = (u - rowmax) - L (reference log_softmax arithmetic; ULP
        // error in L is uniform across tags -> decisions invariant)
        float na = m + ((uv0 - s0.x) - s0.y);
        salpha[cur] = na;                               // safe: all builds done
        ao[t * NT + cur] = na;
        __syncthreads();                                // alphas ready
        uv0 = uv1; s0 = s1;
        uv1 = nuv; s1 = ns;
    }
}

// ---------------------------------------------------------------------------
// Kernel C: terminal argmax + backtrace. trans table in 64KB dynamic smem
// (unevictable, LDS=29cyc on the tag-dependent serial-chain load). Warp 0
// runs the chain with chunked MLP=8 double-buffered __ldcs alphas prefetch.
// ---------------------------------------------------------------------------
__device__ __forceinline__ unsigned fmono(float f) {
    unsigned u = __float_as_uint(f);
    int s = ((int)u) >> 31;
    return u ^ (unsigned)(s | 0x80000000);
}
__device__ __forceinline__ float fmono_inv(unsigned m) {
    return (m & 0x80000000u) ? __uint_as_float(m & 0x7fffffffu)
                             : __uint_as_float(~m);
}

__global__ __launch_bounds__(128) void backtrace_kernel(
    const float* __restrict__ trans,
    float* __restrict__ out)
{
    extern __shared__ __align__(16) float strans[];   // 64KB: full trans table
    int b = blockIdx.x;
    int tid = threadIdx.x;
    int len = g_len[b];
    float* preds = out + (size_t)b * TT;

    const float4* t4 = reinterpret_cast<const float4*>(trans);
    float4* s4 = reinterpret_cast<float4*>(strans);
    #pragma unroll
    for (int i = 0; i < (NT * NT / 4) / 128; i++)
        s4[tid + i * 128] = __ldg(t4 + tid + i * 128);

    for (int t = len + tid; t < TT; t += 128) preds[t] = 0.0f;
    __syncthreads();

    if (tid >= 32) return;   // warps 1-3 done
    int lane = tid;

    const float* ab = g_alphas + (size_t)b * TT * NT;

    // terminal: argmax_cur( alphas[len-1][cur] + trans[EOS][cur] ), first-max ties
    float4 a  = __ldcs(reinterpret_cast<const float4*>(ab + (size_t)(len - 1) * NT) + lane);
    float4 tv = reinterpret_cast<const float4*>(strans + EOS_IDX * NT)[lane];
    unsigned c0 = fmono(a.x + tv.x), c1 = fmono(a.y + tv.y);
    unsigned c2 = fmono(a.z + tv.z), c3 = fmono(a.w + tv.w);
    unsigned best = max(max(c0, c1), max(c2, c3));
    unsigned wmax = __reduce_max_sync(0xffffffffu, best);
    unsigned idx = 0x7fffffffu;
    if (c3 == wmax) idx = 4u * lane + 3u;
    if (c2 == wmax) idx = 4u * lane + 2u;
    if (c1 == wmax) idx = 4u * lane + 1u;
    if (c0 == wmax) idx = 4u * lane + 0u;
    int tag = (int)__reduce_min_sync(0xffffffffu, idx);
    if (lane == 0) {
        out[(size_t)BB * TT + b] = fmono_inv(wmax);  // path score (exact max)
        preds[len - 1] = (float)tag;
    }

    // chase rows R_i = len-2-i for i in [0, nrows); chunked prefetch depth 8
    int nrows = len - 1;
    int nchunks = (nrows + 7) >> 3;
    float4 bufA[8], bufB[8];

#define BT_LOAD(DST, C)                                                        \
    {                                                                          \
        _Pragma("unroll")                                                      \
        for (int k = 0; k < 8; k++) {                                          \
            int i = 8 * (C) + k;                                               \
            if (i < nrows)                                                     \
                DST[k] = __ldcs(reinterpret_cast<const float4*>(               \
                             ab + (size_t)(len - 2 - i) * NT) + lane);         \
        }                                                                      \
    }

#define BT_PROC(SRC, C)                                                        \
    {                                                                          \
        _Pragma("unroll")                                                      \
        for (int k = 0; k < 8; k++) {                                          \
            int i = 8 * (C) + k;                                               \
            if (i >= nrows) break;                                             \
            float4 av = SRC[k];                                                \
            float4 tr = reinterpret_cast<const float4*>(                       \
                            strans + tag * NT)[lane];                          \
            c0 = fmono(av.x + tr.x); c1 = fmono(av.y + tr.y);                  \
            c2 = fmono(av.z + tr.z); c3 = fmono(av.w + tr.w);                  \
            best = max(max(c0, c1), max(c2, c3));                              \
            wmax = __reduce_max_sync(0xffffffffu, best);                       \
            idx = 0x7fffffffu;                                                 \
            if (c3 == wmax) idx = 4u * lane + 3u;                              \
            if (c2 == wmax) idx = 4u * lane + 2u;                              \
            if (c1 == wmax) idx = 4u * lane + 1u;                              \
            if (c0 == wmax) idx = 4u * lane + 0u;                              \
            tag = (int)__reduce_min_sync(0xffffffffu, idx);                    \
            if (lane == 0) preds[len - 2 - i] = (float)tag;                    \
        }                                                                      \
    }

    if (nchunks > 0) BT_LOAD(bufA, 0);
    for (int c = 0; c < nchunks; c++) {
        if ((c & 1) == 0) {
            if (c + 1 < nchunks) BT_LOAD(bufB, c + 1);
            BT_PROC(bufA, c);
        } else {
            if (c + 1 < nchunks) BT_LOAD(bufA, c + 1);
            BT_PROC(bufB, c);
        }
    }
#undef BT_LOAD
#undef BT_PROC
}

// ---------------------------------------------------------------------------
extern "C" void kernel_launch(void* const* d_in, const int* in_sizes, int n_in,
                              void* d_out, int out_size)
{
    const float* u     = (const float*)d_in[0];   // unaries [B,T,N] f32
    const float* trans = (const float*)d_in[1];   // trans  [1,N,N] f32
    const int*   lens  = (const int*)d_in[2];     // lengths [B] (i32 or i64, detected)
    float* out = (float*)d_out;                   // [B*T preds | B scores]

    // 64KB dynamic smem (idempotent attribute sets)
    cudaFuncSetAttribute(backtrace_kernel,
                         cudaFuncAttributeMaxDynamicSharedMemorySize,
                         NT * NT * (int)sizeof(float));
    cudaFuncSetAttribute(prep_kernel,
                         cudaFuncAttributeMaxDynamicSharedMemorySize,
                         NT * NT * (int)sizeof(float));

    lens_kernel<<<1, BB>>>(lens);
    prep_kernel<<<1, 128, NT * NT * sizeof(float)>>>(trans);
    stats_kernel<<<(BB * TT) / 8, 256>>>(u);
    forward_kernel<<<BB, 128>>>(u);
    backtrace_kernel<<<BB, 128, NT * NT * sizeof(float)>>>(trans, out);
}